// round 4
// baseline (speedup 1.0000x reference)
#include <cuda_runtime.h>
#include <math.h>

#define NN   50000
#define EE   800000
#define NE2  850000      // EE + NN self loops
#define HIDD 128

// ---------------- scratch (device globals; no runtime allocation) ----------------
__device__ float g_h  [(size_t)NN * HIDD];
__device__ float g_fs [(size_t)NN * HIDD];
__device__ float g_fd [(size_t)NN * HIDD];
__device__ float g_agg[(size_t)NN * HIDD];
__device__ float g_p  [(size_t)NE2 * 4];    // logits, then p=exp(logit-m)
__device__ float g_m  [(size_t)NN * 4];
__device__ float g_z  [(size_t)NN * 4];

// ---------------- GEMM: h = node_feats @ W_in + b_in  (K=64) ----------------
__global__ __launch_bounds__(256) void k_gemm_in(
    const float* __restrict__ A,     // [NN,64]
    const float* __restrict__ W,     // [64,128]
    const float* __restrict__ bias)  // [128]
{
    __shared__ float As[64][33];
    __shared__ float Bs[32][HIDD];
    int tid = threadIdx.x, tr = tid >> 5, tc = tid & 31;
    int row0 = blockIdx.x * 64;
    float acc[8][4] = {};
    for (int k0 = 0; k0 < 64; k0 += 32) {
        #pragma unroll
        for (int i = 0; i < 8; i++) {
            int idx = tid + i * 256;
            int r = idx >> 5, kk = idx & 31;
            int row = row0 + r;
            As[r][kk] = (row < NN) ? A[(size_t)row * 64 + k0 + kk] : 0.f;
        }
        #pragma unroll
        for (int i = 0; i < 16; i++) {
            int idx = tid + i * 256;
            int kk = idx >> 7, n = idx & 127;
            Bs[kk][n] = W[(size_t)(k0 + kk) * HIDD + n];
        }
        __syncthreads();
        #pragma unroll
        for (int kk = 0; kk < 32; kk++) {
            float a[8];
            #pragma unroll
            for (int i = 0; i < 8; i++) a[i] = As[tr * 8 + i][kk];
            float4 b = *(const float4*)&Bs[kk][tc * 4];
            #pragma unroll
            for (int i = 0; i < 8; i++) {
                acc[i][0] += a[i] * b.x; acc[i][1] += a[i] * b.y;
                acc[i][2] += a[i] * b.z; acc[i][3] += a[i] * b.w;
            }
        }
        __syncthreads();
    }
    float4 bb = *(const float4*)&bias[tc * 4];
    #pragma unroll
    for (int i = 0; i < 8; i++) {
        int row = row0 + tr * 8 + i;
        if (row < NN) {
            float4 o = { acc[i][0] + bb.x, acc[i][1] + bb.y,
                         acc[i][2] + bb.z, acc[i][3] + bb.w };
            *(float4*)&g_h[(size_t)row * HIDD + tc * 4] = o;
        }
    }
}

// ---------------- dual GEMM: fs = h@Ws+bs, fd = h@Wd+bd (K=128) ----------------
__global__ __launch_bounds__(256) void k_gemm_dual(
    const float* __restrict__ Ws, const float* __restrict__ bs,
    const float* __restrict__ Wd, const float* __restrict__ bd)
{
    __shared__ float As[32][33];
    __shared__ float Bs[32][HIDD];
    __shared__ float Bd[32][HIDD];
    int tid = threadIdx.x, tr = tid >> 5, tc = tid & 31;
    int row0 = blockIdx.x * 32;
    float cs[4][4] = {}, cd[4][4] = {};
    for (int k0 = 0; k0 < HIDD; k0 += 32) {
        #pragma unroll
        for (int i = 0; i < 4; i++) {
            int idx = tid + i * 256;
            int r = idx >> 5, kk = idx & 31;
            int row = row0 + r;
            As[r][kk] = (row < NN) ? g_h[(size_t)row * HIDD + k0 + kk] : 0.f;
        }
        #pragma unroll
        for (int i = 0; i < 16; i++) {
            int idx = tid + i * 256;
            int kk = idx >> 7, n = idx & 127;
            Bs[kk][n] = Ws[(size_t)(k0 + kk) * HIDD + n];
            Bd[kk][n] = Wd[(size_t)(k0 + kk) * HIDD + n];
        }
        __syncthreads();
        #pragma unroll
        for (int kk = 0; kk < 32; kk++) {
            float a[4];
            #pragma unroll
            for (int i = 0; i < 4; i++) a[i] = As[tr * 4 + i][kk];
            float4 vs = *(const float4*)&Bs[kk][tc * 4];
            float4 vd = *(const float4*)&Bd[kk][tc * 4];
            #pragma unroll
            for (int i = 0; i < 4; i++) {
                cs[i][0] += a[i] * vs.x; cs[i][1] += a[i] * vs.y;
                cs[i][2] += a[i] * vs.z; cs[i][3] += a[i] * vs.w;
                cd[i][0] += a[i] * vd.x; cd[i][1] += a[i] * vd.y;
                cd[i][2] += a[i] * vd.z; cd[i][3] += a[i] * vd.w;
            }
        }
        __syncthreads();
    }
    float4 vbs = *(const float4*)&bs[tc * 4];
    float4 vbd = *(const float4*)&bd[tc * 4];
    #pragma unroll
    for (int i = 0; i < 4; i++) {
        int row = row0 + tr * 4 + i;
        if (row < NN) {
            float4 o;
            o.x = cs[i][0] + vbs.x; o.y = cs[i][1] + vbs.y;
            o.z = cs[i][2] + vbs.z; o.w = cs[i][3] + vbs.w;
            *(float4*)&g_fs[(size_t)row * HIDD + tc * 4] = o;
            o.x = cd[i][0] + vbd.x; o.y = cd[i][1] + vbd.y;
            o.z = cd[i][2] + vbd.z; o.w = cd[i][3] + vbd.w;
            *(float4*)&g_fd[(size_t)row * HIDD + tc * 4] = o;
        }
    }
}

// ---------------- per-layer init: agg = 0, m = -inf, z = 0 ----------------
__global__ void k_init()
{
    int i = blockIdx.x * blockDim.x + threadIdx.x;
    if (i < NN * HIDD) g_agg[i] = 0.f;
    if (i < NN * 4) { g_m[i] = -INFINITY; g_z[i] = 0.f; }
}

// ---------------- edge logits + segment max (warp per edge) ----------------
__global__ __launch_bounds__(256) void k_logits(
    const int* __restrict__ src, const int* __restrict__ dst,
    const float* __restrict__ attn)   // [4*32] for this layer
{
    int w = (blockIdx.x * 256 + threadIdx.x) >> 5;
    int lane = threadIdx.x & 31;
    if (w >= NE2) return;
    int s, d;
    if (w < EE) { s = src[w]; d = dst[w]; } else { s = w - EE; d = s; }
    float4 a = *(const float4*)(g_fs + (size_t)s * HIDD + lane * 4);
    float4 b = *(const float4*)(g_fd + (size_t)d * HIDD + lane * 4);
    float4 wa = *(const float4*)(attn + lane * 4);
    float x0 = a.x + b.x; x0 = x0 > 0.f ? x0 : 0.2f * x0;
    float x1 = a.y + b.y; x1 = x1 > 0.f ? x1 : 0.2f * x1;
    float x2 = a.z + b.z; x2 = x2 > 0.f ? x2 : 0.2f * x2;
    float x3 = a.w + b.w; x3 = x3 > 0.f ? x3 : 0.2f * x3;
    float p = x0 * wa.x + x1 * wa.y + x2 * wa.z + x3 * wa.w;
    p += __shfl_down_sync(0xffffffffu, p, 4);
    p += __shfl_down_sync(0xffffffffu, p, 2);
    p += __shfl_down_sync(0xffffffffu, p, 1);
    if ((lane & 7) == 0) {
        int head = lane >> 3;
        g_p[(size_t)w * 4 + head] = p;
        float* ma = &g_m[(size_t)d * 4 + head];
        if (p >= 0.f) atomicMax((int*)ma, __float_as_int(p));
        else          atomicMin((unsigned int*)ma, (unsigned int)__float_as_int(p));
    }
}

// ---------------- exp + segment sum (thread per edge*head) ----------------
__global__ void k_exp(const int* __restrict__ dst)
{
    int i = blockIdx.x * blockDim.x + threadIdx.x;
    if (i >= NE2 * 4) return;
    int e = i >> 2, h = i & 3;
    int d = (e < EE) ? dst[e] : e - EE;
    float p = __expf(g_p[i] - g_m[d * 4 + h]);
    g_p[i] = p;
    atomicAdd(&g_z[d * 4 + h], p);
}

// ---------------- weighted scatter (warp per edge) ----------------
__global__ __launch_bounds__(256) void k_scatter(
    const int* __restrict__ src, const int* __restrict__ dst)
{
    int w = (blockIdx.x * 256 + threadIdx.x) >> 5;
    int lane = threadIdx.x & 31;
    if (w >= NE2) return;
    int s, d;
    if (w < EE) { s = src[w]; d = dst[w]; } else { s = w - EE; d = s; }
    int head = lane >> 3;
    float alpha = g_p[(size_t)w * 4 + head] / g_z[(size_t)d * 4 + head];
    float4 a = *(const float4*)(g_fs + (size_t)s * HIDD + lane * 4);
    float* o = g_agg + (size_t)d * HIDD + lane * 4;
    atomicAdd(o + 0, a.x * alpha);
    atomicAdd(o + 1, a.y * alpha);
    atomicAdd(o + 2, a.z * alpha);
    atomicAdd(o + 3, a.w * alpha);
}

// ---------------- LN(2h + agg)*g + b, ReLU (warp per node) ----------------
__global__ __launch_bounds__(256) void k_ln(
    const float* __restrict__ g, const float* __restrict__ b,
    float* __restrict__ outh)   // optional copy target (last layer), may be null
{
    int w = (blockIdx.x * 256 + threadIdx.x) >> 5;
    int lane = threadIdx.x & 31;
    if (w >= NN) return;
    size_t base = (size_t)w * HIDD + lane * 4;
    float4 hv = *(const float4*)(g_h + base);
    float4 av = *(const float4*)(g_agg + base);
    float x0 = 2.f * hv.x + av.x;
    float x1 = 2.f * hv.y + av.y;
    float x2 = 2.f * hv.z + av.z;
    float x3 = 2.f * hv.w + av.w;
    float su = x0 + x1 + x2 + x3;
    #pragma unroll
    for (int o = 16; o; o >>= 1) su += __shfl_xor_sync(0xffffffffu, su, o);
    float mu = su * (1.f / 128.f);
    float d0 = x0 - mu, d1 = x1 - mu, d2 = x2 - mu, d3 = x3 - mu;
    float sv = d0 * d0 + d1 * d1 + d2 * d2 + d3 * d3;
    #pragma unroll
    for (int o = 16; o; o >>= 1) sv += __shfl_xor_sync(0xffffffffu, sv, o);
    float inv = rsqrtf(sv * (1.f / 128.f) + 1e-5f);
    float4 gg = *(const float4*)(g + lane * 4);
    float4 bb = *(const float4*)(b + lane * 4);
    float y0 = fmaxf(d0 * inv * gg.x + bb.x, 0.f);
    float y1 = fmaxf(d1 * inv * gg.y + bb.y, 0.f);
    float y2 = fmaxf(d2 * inv * gg.z + bb.z, 0.f);
    float y3 = fmaxf(d3 * inv * gg.w + bb.w, 0.f);
    float4 y = { y0, y1, y2, y3 };
    *(float4*)(g_h + base) = y;
    if (outh) *(float4*)(outh + base) = y;
}

// ---------------- graph mean ----------------
__global__ void k_zero_out(float* __restrict__ out)
{
    if (threadIdx.x < 128) out[threadIdx.x] = 0.f;
}

__global__ void k_mean(float* __restrict__ out)
{
    int c = threadIdx.x;              // 128 threads = feature
    int chunk = (NN + gridDim.x - 1) / gridDim.x;
    int n0 = blockIdx.x * chunk;
    int n1 = n0 + chunk; if (n1 > NN) n1 = NN;
    float s = 0.f;
    for (int n = n0; n < n1; n++) s += g_h[(size_t)n * HIDD + c];
    atomicAdd(&out[c], s * (1.f / (float)NN));
}

// ---------------- launch ----------------
extern "C" void kernel_launch(void* const* d_in, const int* in_sizes, int n_in,
                              void* d_out, int out_size)
{
    const float* nf    = (const float*)d_in[0];
    const int*   src   = (const int*)  d_in[1];
    const int*   dst   = (const int*)  d_in[2];
    const float* W_in  = (const float*)d_in[3];
    const float* b_in  = (const float*)d_in[4];
    const float* W_src = (const float*)d_in[5];
    const float* b_src = (const float*)d_in[6];
    const float* W_dst = (const float*)d_in[7];
    const float* b_dst = (const float*)d_in[8];
    const float* attn  = (const float*)d_in[9];
    const float* ln_g  = (const float*)d_in[10];
    const float* ln_b  = (const float*)d_in[11];
    float* out = (float*)d_out;

    (void)in_sizes; (void)n_in; (void)out_size;

    k_gemm_in<<<(NN + 63) / 64, 256>>>(nf, W_in, b_in);

    const int gEdgeWarp = (NE2 * 32 + 255) / 256;     // warp-per-edge grids
    const int gExp      = (NE2 * 4 + 255) / 256;
    const int gInit     = (NN * HIDD + 255) / 256;
    const int gNodeWarp = (NN * 32 + 255) / 256;

    for (int l = 0; l < 3; l++) {
        k_gemm_dual<<<(NN + 31) / 32, 256>>>(
            W_src + (size_t)l * HIDD * HIDD, b_src + (size_t)l * HIDD,
            W_dst + (size_t)l * HIDD * HIDD, b_dst + (size_t)l * HIDD);
        k_init<<<gInit, 256>>>();
        k_logits<<<gEdgeWarp, 256>>>(src, dst, attn + (size_t)l * HIDD);
        k_exp<<<gExp, 256>>>(dst);
        k_scatter<<<gEdgeWarp, 256>>>(src, dst);
        k_ln<<<gNodeWarp, 256>>>(ln_g + (size_t)l * HIDD, ln_b + (size_t)l * HIDD,
                                 (l == 2) ? (out + HIDD) : nullptr);
    }

    k_zero_out<<<1, 128>>>(out);
    k_mean<<<128, 128>>>(out);
}

// round 6
// speedup vs baseline: 2.3728x; 2.3728x over previous
#include <cuda_runtime.h>
#include <math.h>

#define NN   50000
#define EE   800000
#define NE2  850000      // EE + NN self loops
#define HIDD 128
#define NB   196         // ceil(NN/256) scan blocks

// ---------------- scratch (device globals; no runtime allocation) ----------------
__device__ float g_h  [(size_t)NN * HIDD];
__device__ float g_fs [(size_t)NN * HIDD];
__device__ float g_fd [(size_t)NN * HIDD];
__device__ float g_p  [(size_t)NE2 * 4];    // p = exp(logit), CSR slot order
__device__ int   g_csr_src[NE2];
__device__ int   g_rowptr [NN + 1];
__device__ int   g_cursor [NN];             // doubles as histogram counts
__device__ int   g_bsum[NB];
__device__ int   g_boff[NB];

// ================= CSR build (per launch; dst-only, layer-invariant) =============
__global__ void k_zero_cnt()
{
    int i = blockIdx.x * blockDim.x + threadIdx.x;
    if (i < NN) g_cursor[i] = 0;
}

__global__ void k_hist(const int* __restrict__ dst)
{
    int e = blockIdx.x * blockDim.x + threadIdx.x;
    if (e >= NE2) return;
    int d = (e < EE) ? dst[e] : e - EE;
    atomicAdd(&g_cursor[d], 1);
}

__global__ void k_scan1()
{
    __shared__ int s[256];
    int t = threadIdx.x, i = blockIdx.x * 256 + t;
    int v = (i < NN) ? g_cursor[i] : 0;
    s[t] = v; __syncthreads();
    for (int o = 1; o < 256; o <<= 1) {
        int x = (t >= o) ? s[t - o] : 0;
        __syncthreads();
        s[t] += x;
        __syncthreads();
    }
    if (i < NN) g_rowptr[i] = s[t] - v;          // block-local exclusive
    if (t == 255) g_bsum[blockIdx.x] = s[255];
}

__global__ void k_scan2()
{
    __shared__ int s[256];
    int t = threadIdx.x;
    int v = (t < NB) ? g_bsum[t] : 0;
    s[t] = v; __syncthreads();
    for (int o = 1; o < 256; o <<= 1) {
        int x = (t >= o) ? s[t - o] : 0;
        __syncthreads();
        s[t] += x;
        __syncthreads();
    }
    if (t < NB) g_boff[t] = s[t] - v;            // exclusive block offsets
}

__global__ void k_scan3()
{
    int i = blockIdx.x * blockDim.x + threadIdx.x;
    if (i < NN) {
        int rp = g_rowptr[i] + g_boff[i >> 8];
        g_rowptr[i] = rp;
        g_cursor[i] = rp;                        // fill cursor
    }
    if (i == 0) g_rowptr[NN] = NE2;
}

__global__ void k_fill(const int* __restrict__ src, const int* __restrict__ dst)
{
    int e = blockIdx.x * blockDim.x + threadIdx.x;
    if (e >= NE2) return;
    int s, d;
    if (e < EE) { s = src[e]; d = dst[e]; } else { s = e - EE; d = s; }
    int pos = atomicAdd(&g_cursor[d], 1);
    g_csr_src[pos] = s;
}

// ---------------- GEMM: h = node_feats @ W_in + b_in  (K=64) ----------------
__global__ __launch_bounds__(256) void k_gemm_in(
    const float* __restrict__ A,     // [NN,64]
    const float* __restrict__ W,     // [64,128]
    const float* __restrict__ bias)  // [128]
{
    __shared__ float As[64][33];
    __shared__ float Bs[32][HIDD];
    int tid = threadIdx.x, tr = tid >> 5, tc = tid & 31;
    int row0 = blockIdx.x * 64;
    float acc[8][4] = {};
    for (int k0 = 0; k0 < 64; k0 += 32) {
        #pragma unroll
        for (int i = 0; i < 8; i++) {
            int idx = tid + i * 256;
            int r = idx >> 5, kk = idx & 31;
            int row = row0 + r;
            As[r][kk] = (row < NN) ? A[(size_t)row * 64 + k0 + kk] : 0.f;
        }
        #pragma unroll
        for (int i = 0; i < 16; i++) {
            int idx = tid + i * 256;
            int kk = idx >> 7, n = idx & 127;
            Bs[kk][n] = W[(size_t)(k0 + kk) * HIDD + n];
        }
        __syncthreads();
        #pragma unroll
        for (int kk = 0; kk < 32; kk++) {
            float a[8];
            #pragma unroll
            for (int i = 0; i < 8; i++) a[i] = As[tr * 8 + i][kk];
            float4 b = *(const float4*)&Bs[kk][tc * 4];
            #pragma unroll
            for (int i = 0; i < 8; i++) {
                acc[i][0] += a[i] * b.x; acc[i][1] += a[i] * b.y;
                acc[i][2] += a[i] * b.z; acc[i][3] += a[i] * b.w;
            }
        }
        __syncthreads();
    }
    float4 bb = *(const float4*)&bias[tc * 4];
    #pragma unroll
    for (int i = 0; i < 8; i++) {
        int row = row0 + tr * 8 + i;
        if (row < NN) {
            float4 o = { acc[i][0] + bb.x, acc[i][1] + bb.y,
                         acc[i][2] + bb.z, acc[i][3] + bb.w };
            *(float4*)&g_h[(size_t)row * HIDD + tc * 4] = o;
        }
    }
}

// ---------------- dual GEMM: fs = h@Ws+bs, fd = h@Wd+bd (K=128) ----------------
__global__ __launch_bounds__(256) void k_gemm_dual(
    const float* __restrict__ Ws, const float* __restrict__ bs,
    const float* __restrict__ Wd, const float* __restrict__ bd)
{
    __shared__ float As[32][33];
    __shared__ float Bs[32][HIDD];
    __shared__ float Bd[32][HIDD];
    int tid = threadIdx.x, tr = tid >> 5, tc = tid & 31;
    int row0 = blockIdx.x * 32;
    float cs[4][4] = {}, cd[4][4] = {};
    for (int k0 = 0; k0 < HIDD; k0 += 32) {
        #pragma unroll
        for (int i = 0; i < 4; i++) {
            int idx = tid + i * 256;
            int r = idx >> 5, kk = idx & 31;
            int row = row0 + r;
            As[r][kk] = (row < NN) ? g_h[(size_t)row * HIDD + k0 + kk] : 0.f;
        }
        #pragma unroll
        for (int i = 0; i < 16; i++) {
            int idx = tid + i * 256;
            int kk = idx >> 7, n = idx & 127;
            Bs[kk][n] = Ws[(size_t)(k0 + kk) * HIDD + n];
            Bd[kk][n] = Wd[(size_t)(k0 + kk) * HIDD + n];
        }
        __syncthreads();
        #pragma unroll
        for (int kk = 0; kk < 32; kk++) {
            float a[4];
            #pragma unroll
            for (int i = 0; i < 4; i++) a[i] = As[tr * 4 + i][kk];
            float4 vs = *(const float4*)&Bs[kk][tc * 4];
            float4 vd = *(const float4*)&Bd[kk][tc * 4];
            #pragma unroll
            for (int i = 0; i < 4; i++) {
                cs[i][0] += a[i] * vs.x; cs[i][1] += a[i] * vs.y;
                cs[i][2] += a[i] * vs.z; cs[i][3] += a[i] * vs.w;
                cd[i][0] += a[i] * vd.x; cd[i][1] += a[i] * vd.y;
                cd[i][2] += a[i] * vd.z; cd[i][3] += a[i] * vd.w;
            }
        }
        __syncthreads();
    }
    float4 vbs = *(const float4*)&bs[tc * 4];
    float4 vbd = *(const float4*)&bd[tc * 4];
    #pragma unroll
    for (int i = 0; i < 4; i++) {
        int row = row0 + tr * 4 + i;
        if (row < NN) {
            float4 o;
            o.x = cs[i][0] + vbs.x; o.y = cs[i][1] + vbs.y;
            o.z = cs[i][2] + vbs.z; o.w = cs[i][3] + vbs.w;
            *(float4*)&g_fs[(size_t)row * HIDD + tc * 4] = o;
            o.x = cd[i][0] + vbd.x; o.y = cd[i][1] + vbd.y;
            o.z = cd[i][2] + vbd.z; o.w = cd[i][3] + vbd.w;
            *(float4*)&g_fd[(size_t)row * HIDD + tc * 4] = o;
        }
    }
}

// ====== fused attention + aggregation + residual + LN + ReLU (warp per node) =====
// Unshifted softmax: p = exp(logit). Mathematically identical to max-shifted
// softmax; logits are bounded (|x| < ~10 given 0.1-scaled weights), no overflow.
__global__ __launch_bounds__(256) void k_agg_ln(
    const float* __restrict__ attn,   // [4*32] this layer
    const float* __restrict__ lng, const float* __restrict__ lnb,
    float* __restrict__ outh)         // last-layer copy target or null
{
    int n = (blockIdx.x * 256 + threadIdx.x) >> 5;
    int lane = threadIdx.x & 31;
    if (n >= NN) return;
    int head = lane >> 3;

    float4 fdv = *(const float4*)(g_fd + (size_t)n * HIDD + lane * 4);
    float4 wa  = *(const float4*)(attn + lane * 4);

    int beg = g_rowptr[n], end = g_rowptr[n + 1];

    // ---- pass 1: logits -> p, accumulate z per head ----
    float z_acc = 0.f;
    for (int i = beg; i < end; i++) {
        int s = g_csr_src[i];
        float4 a = *(const float4*)(g_fs + (size_t)s * HIDD + lane * 4);
        float x0 = a.x + fdv.x; x0 = x0 > 0.f ? x0 : 0.2f * x0;
        float x1 = a.y + fdv.y; x1 = x1 > 0.f ? x1 : 0.2f * x1;
        float x2 = a.z + fdv.z; x2 = x2 > 0.f ? x2 : 0.2f * x2;
        float x3 = a.w + fdv.w; x3 = x3 > 0.f ? x3 : 0.2f * x3;
        float lg = x0 * wa.x + x1 * wa.y + x2 * wa.z + x3 * wa.w;
        lg += __shfl_xor_sync(0xffffffffu, lg, 4);
        lg += __shfl_xor_sync(0xffffffffu, lg, 2);
        lg += __shfl_xor_sync(0xffffffffu, lg, 1);   // all 8 lanes of group hold it
        float p = __expf(lg);
        z_acc += p;
        if ((lane & 7) == 0) g_p[(size_t)i * 4 + head] = p;
    }
    float inv_z = 1.f / z_acc;

    // ---- pass 2: weighted gather into registers ----
    float m0 = 0.f, m1 = 0.f, m2 = 0.f, m3 = 0.f;
    for (int i = beg; i < end; i++) {
        int s = g_csr_src[i];
        float al = g_p[(size_t)i * 4 + head] * inv_z;
        float4 a = *(const float4*)(g_fs + (size_t)s * HIDD + lane * 4);
        m0 += a.x * al; m1 += a.y * al; m2 += a.z * al; m3 += a.w * al;
    }

    // ---- residual + LN + ReLU ----
    size_t base = (size_t)n * HIDD + lane * 4;
    float4 hv = *(const float4*)(g_h + base);
    float x0 = 2.f * hv.x + m0;
    float x1 = 2.f * hv.y + m1;
    float x2 = 2.f * hv.z + m2;
    float x3 = 2.f * hv.w + m3;
    float su = x0 + x1 + x2 + x3;
    #pragma unroll
    for (int o = 16; o; o >>= 1) su += __shfl_xor_sync(0xffffffffu, su, o);
    float mu = su * (1.f / 128.f);
    float d0 = x0 - mu, d1 = x1 - mu, d2 = x2 - mu, d3 = x3 - mu;
    float sv = d0 * d0 + d1 * d1 + d2 * d2 + d3 * d3;
    #pragma unroll
    for (int o = 16; o; o >>= 1) sv += __shfl_xor_sync(0xffffffffu, sv, o);
    float inv = rsqrtf(sv * (1.f / 128.f) + 1e-5f);
    float4 gg = *(const float4*)(lng + lane * 4);
    float4 bb = *(const float4*)(lnb + lane * 4);
    float y0 = fmaxf(d0 * inv * gg.x + bb.x, 0.f);
    float y1 = fmaxf(d1 * inv * gg.y + bb.y, 0.f);
    float y2 = fmaxf(d2 * inv * gg.z + bb.z, 0.f);
    float y3 = fmaxf(d3 * inv * gg.w + bb.w, 0.f);
    float4 y = { y0, y1, y2, y3 };
    *(float4*)(g_h + base) = y;
    if (outh) *(float4*)(outh + base) = y;
}

// ---------------- graph mean ----------------
__global__ void k_zero_out(float* __restrict__ out)
{
    if (threadIdx.x < 128) out[threadIdx.x] = 0.f;
}

__global__ void k_mean(float* __restrict__ out)
{
    int c = threadIdx.x;              // 128 threads = feature
    int chunk = (NN + gridDim.x - 1) / gridDim.x;
    int n0 = blockIdx.x * chunk;
    int n1 = n0 + chunk; if (n1 > NN) n1 = NN;
    float s = 0.f;
    for (int n = n0; n < n1; n++) s += g_h[(size_t)n * HIDD + c];
    atomicAdd(&out[c], s * (1.f / (float)NN));
}

// ---------------- launch ----------------
extern "C" void kernel_launch(void* const* d_in, const int* in_sizes, int n_in,
                              void* d_out, int out_size)
{
    const float* nf    = (const float*)d_in[0];
    const int*   src   = (const int*)  d_in[1];
    const int*   dst   = (const int*)  d_in[2];
    const float* W_in  = (const float*)d_in[3];
    const float* b_in  = (const float*)d_in[4];
    const float* W_src = (const float*)d_in[5];
    const float* b_src = (const float*)d_in[6];
    const float* W_dst = (const float*)d_in[7];
    const float* b_dst = (const float*)d_in[8];
    const float* attn  = (const float*)d_in[9];
    const float* ln_g  = (const float*)d_in[10];
    const float* ln_b  = (const float*)d_in[11];
    float* out = (float*)d_out;

    (void)in_sizes; (void)n_in; (void)out_size;

    const int gE = (NE2 + 255) / 256;
    const int gN = (NN + 255) / 256;

    // CSR build (dst-sorted), once per launch
    k_zero_cnt<<<gN, 256>>>();
    k_hist<<<gE, 256>>>(dst);
    k_scan1<<<NB, 256>>>();
    k_scan2<<<1, 256>>>();
    k_scan3<<<gN, 256>>>();
    k_fill<<<gE, 256>>>(src, dst);

    k_gemm_in<<<(NN + 63) / 64, 256>>>(nf, W_in, b_in);

    const int gNodeWarp = (NN * 32 + 255) / 256;

    for (int l = 0; l < 3; l++) {
        k_gemm_dual<<<(NN + 31) / 32, 256>>>(
            W_src + (size_t)l * HIDD * HIDD, b_src + (size_t)l * HIDD,
            W_dst + (size_t)l * HIDD * HIDD, b_dst + (size_t)l * HIDD);
        k_agg_ln<<<gNodeWarp, 256>>>(
            attn + (size_t)l * HIDD,
            ln_g + (size_t)l * HIDD, ln_b + (size_t)l * HIDD,
            (l == 2) ? (out + HIDD) : nullptr);
    }

    k_zero_out<<<1, 128>>>(out);
    k_mean<<<128, 128>>>(out);
}

// round 8
// speedup vs baseline: 4.0621x; 1.7120x over previous
#include <cuda_runtime.h>
#include <math.h>
#include <stdint.h>

#define NN   50000
#define EE   800000
#define NE2  850000      // EE + NN self loops
#define HIDD 128
#define NB   196         // ceil(NN/256) scan blocks

// ---------------- scratch (device globals; no runtime allocation) ----------------
__device__ float g_h  [(size_t)NN * HIDD];
__device__ float g_fs [(size_t)NN * HIDD];
__device__ float g_fd [(size_t)NN * HIDD];
__device__ int   g_csr_src[NE2];
__device__ int   g_rowptr [NN + 1];
__device__ int   g_cursor [NN];             // doubles as histogram counts
__device__ int   g_bsum[NB];
__device__ int   g_boff[NB];

// ================= CSR build (per launch; dst-only, layer-invariant) =============
__global__ void k_zero_cnt()
{
    int i = blockIdx.x * blockDim.x + threadIdx.x;
    if (i < NN) g_cursor[i] = 0;
}

__global__ void k_hist(const int* __restrict__ dst)
{
    int e = blockIdx.x * blockDim.x + threadIdx.x;
    if (e >= NE2) return;
    int d = (e < EE) ? dst[e] : e - EE;
    atomicAdd(&g_cursor[d], 1);
}

__global__ void k_scan1()
{
    __shared__ int s[256];
    int t = threadIdx.x, i = blockIdx.x * 256 + t;
    int v = (i < NN) ? g_cursor[i] : 0;
    s[t] = v; __syncthreads();
    for (int o = 1; o < 256; o <<= 1) {
        int x = (t >= o) ? s[t - o] : 0;
        __syncthreads();
        s[t] += x;
        __syncthreads();
    }
    if (i < NN) g_rowptr[i] = s[t] - v;          // block-local exclusive
    if (t == 255) g_bsum[blockIdx.x] = s[255];
}

__global__ void k_scan2()
{
    __shared__ int s[256];
    int t = threadIdx.x;
    int v = (t < NB) ? g_bsum[t] : 0;
    s[t] = v; __syncthreads();
    for (int o = 1; o < 256; o <<= 1) {
        int x = (t >= o) ? s[t - o] : 0;
        __syncthreads();
        s[t] += x;
        __syncthreads();
    }
    if (t < NB) g_boff[t] = s[t] - v;            // exclusive block offsets
}

__global__ void k_scan3()
{
    int i = blockIdx.x * blockDim.x + threadIdx.x;
    if (i < NN) {
        int rp = g_rowptr[i] + g_boff[i >> 8];
        g_rowptr[i] = rp;
        g_cursor[i] = rp;                        // fill cursor
    }
    if (i == 0) g_rowptr[NN] = NE2;
}

__global__ void k_fill(const int* __restrict__ src, const int* __restrict__ dst)
{
    int e = blockIdx.x * blockDim.x + threadIdx.x;
    if (e >= NE2) return;
    int s, d;
    if (e < EE) { s = src[e]; d = dst[e]; } else { s = e - EE; d = s; }
    int pos = atomicAdd(&g_cursor[d], 1);
    g_csr_src[pos] = s;
}

// ---------------- GEMM: h = node_feats @ W_in + b_in  (K=64, fp32 SIMT) ----------
__global__ __launch_bounds__(256) void k_gemm_in(
    const float* __restrict__ A,     // [NN,64]
    const float* __restrict__ W,     // [64,128]
    const float* __restrict__ bias)  // [128]
{
    __shared__ float As[64][33];
    __shared__ float Bs[32][HIDD];
    int tid = threadIdx.x, tr = tid >> 5, tc = tid & 31;
    int row0 = blockIdx.x * 64;
    float acc[8][4] = {};
    for (int k0 = 0; k0 < 64; k0 += 32) {
        #pragma unroll
        for (int i = 0; i < 8; i++) {
            int idx = tid + i * 256;
            int r = idx >> 5, kk = idx & 31;
            int row = row0 + r;
            As[r][kk] = (row < NN) ? A[(size_t)row * 64 + k0 + kk] : 0.f;
        }
        #pragma unroll
        for (int i = 0; i < 16; i++) {
            int idx = tid + i * 256;
            int kk = idx >> 7, n = idx & 127;
            Bs[kk][n] = W[(size_t)(k0 + kk) * HIDD + n];
        }
        __syncthreads();
        #pragma unroll
        for (int kk = 0; kk < 32; kk++) {
            float a[8];
            #pragma unroll
            for (int i = 0; i < 8; i++) a[i] = As[tr * 8 + i][kk];
            float4 b = *(const float4*)&Bs[kk][tc * 4];
            #pragma unroll
            for (int i = 0; i < 8; i++) {
                acc[i][0] += a[i] * b.x; acc[i][1] += a[i] * b.y;
                acc[i][2] += a[i] * b.z; acc[i][3] += a[i] * b.w;
            }
        }
        __syncthreads();
    }
    float4 bb = *(const float4*)&bias[tc * 4];
    #pragma unroll
    for (int i = 0; i < 8; i++) {
        int row = row0 + tr * 8 + i;
        if (row < NN) {
            float4 o = { acc[i][0] + bb.x, acc[i][1] + bb.y,
                         acc[i][2] + bb.z, acc[i][3] + bb.w };
            *(float4*)&g_h[(size_t)row * HIDD + tc * 4] = o;
        }
    }
}

// ============ tf32 tensor-core dual GEMM: F = h @ W + b  (M=NN, N=128, K=128) ====
// grid.y = 0 -> (Ws, bs, g_fs);  grid.y = 1 -> (Wd, bd, g_fd)
__device__ __forceinline__ float to_tf32(float x)
{
    uint32_t r;
    asm("cvt.rna.tf32.f32 %0, %1;" : "=r"(r) : "f"(x));
    return __uint_as_float(r);
}

__device__ __forceinline__ void mma_tf32(
    float& c0, float& c1, float& c2, float& c3,
    uint32_t a0, uint32_t a1, uint32_t a2, uint32_t a3,
    uint32_t b0, uint32_t b1)
{
    asm volatile(
        "mma.sync.aligned.m16n8k8.row.col.f32.tf32.tf32.f32 "
        "{%0,%1,%2,%3},{%4,%5,%6,%7},{%8,%9},{%0,%1,%2,%3};"
        : "+f"(c0), "+f"(c1), "+f"(c2), "+f"(c3)
        : "r"(a0), "r"(a1), "r"(a2), "r"(a3), "r"(b0), "r"(b1));
}

__global__ __launch_bounds__(256, 2) void k_gemm_dual_tc(
    const float* __restrict__ Ws, const float* __restrict__ bs,
    const float* __restrict__ Wd, const float* __restrict__ bd)
{
    __shared__ float As[128][36];   // [m][k], +4 pad: frag loads conflict-free
    __shared__ float Bs[32][132];   // [k][n], +4 pad
    const float* W    = blockIdx.y ? Wd : Ws;
    const float* bias = blockIdx.y ? bd : bs;
    float*       F    = blockIdx.y ? g_fd : g_fs;

    int tid = threadIdx.x;
    int lane = tid & 31, wid = tid >> 5;
    int wm = wid >> 2, wn = wid & 3;          // warp grid 2(m) x 4(n)
    int l4 = lane >> 2, lk = lane & 3;
    int row0 = blockIdx.x * 128;

    float c[4][4][4];
    #pragma unroll
    for (int i = 0; i < 4; i++)
        #pragma unroll
        for (int j = 0; j < 4; j++)
            #pragma unroll
            for (int q = 0; q < 4; q++) c[i][j][q] = 0.f;

    for (int k0 = 0; k0 < HIDD; k0 += 32) {
        // stage A tile 128x32 (convert to tf32 during store)
        #pragma unroll
        for (int i = 0; i < 4; i++) {
            int idx = tid + i * 256;
            int r = idx >> 3, cc = (idx & 7) * 4;
            int row = row0 + r;
            float4 v = { 0.f, 0.f, 0.f, 0.f };
            if (row < NN) v = *(const float4*)&g_h[(size_t)row * HIDD + k0 + cc];
            v.x = to_tf32(v.x); v.y = to_tf32(v.y);
            v.z = to_tf32(v.z); v.w = to_tf32(v.w);
            *(float4*)&As[r][cc] = v;
        }
        // stage B tile 32x128
        #pragma unroll
        for (int i = 0; i < 4; i++) {
            int idx = tid + i * 256;
            int kk = idx >> 5, cc = (idx & 31) * 4;
            float4 v = *(const float4*)&W[(size_t)(k0 + kk) * HIDD + cc];
            v.x = to_tf32(v.x); v.y = to_tf32(v.y);
            v.z = to_tf32(v.z); v.w = to_tf32(v.w);
            *(float4*)&Bs[kk][cc] = v;
        }
        __syncthreads();

        #pragma unroll
        for (int ks = 0; ks < 4; ks++) {
            int kc = ks * 8 + lk;
            uint32_t a[4][4], b[4][2];
            #pragma unroll
            for (int mf = 0; mf < 4; mf++) {
                int m0 = wm * 64 + mf * 16;
                a[mf][0] = __float_as_uint(As[m0 + l4    ][kc    ]);
                a[mf][1] = __float_as_uint(As[m0 + l4 + 8][kc    ]);
                a[mf][2] = __float_as_uint(As[m0 + l4    ][kc + 4]);
                a[mf][3] = __float_as_uint(As[m0 + l4 + 8][kc + 4]);
            }
            #pragma unroll
            for (int nf = 0; nf < 4; nf++) {
                int n0 = wn * 32 + nf * 8 + l4;
                b[nf][0] = __float_as_uint(Bs[ks * 8 + lk    ][n0]);
                b[nf][1] = __float_as_uint(Bs[ks * 8 + lk + 4][n0]);
            }
            #pragma unroll
            for (int mf = 0; mf < 4; mf++)
                #pragma unroll
                for (int nf = 0; nf < 4; nf++)
                    mma_tf32(c[mf][nf][0], c[mf][nf][1], c[mf][nf][2], c[mf][nf][3],
                             a[mf][0], a[mf][1], a[mf][2], a[mf][3],
                             b[nf][0], b[nf][1]);
        }
        __syncthreads();
    }

    // epilogue: bias + store (c0,c1 -> row g cols 2t,2t+1; c2,c3 -> row g+8)
    #pragma unroll
    for (int mf = 0; mf < 4; mf++) {
        int r = row0 + wm * 64 + mf * 16 + l4;
        #pragma unroll
        for (int nf = 0; nf < 4; nf++) {
            int col = wn * 32 + nf * 8 + lk * 2;
            float2 bb = *(const float2*)&bias[col];
            if (r < NN) {
                float2 o = { c[mf][nf][0] + bb.x, c[mf][nf][1] + bb.y };
                *(float2*)&F[(size_t)r * HIDD + col] = o;
            }
            if (r + 8 < NN) {
                float2 o = { c[mf][nf][2] + bb.x, c[mf][nf][3] + bb.y };
                *(float2*)&F[(size_t)(r + 8) * HIDD + col] = o;
            }
        }
    }
}

// ====== fused single-pass attention + aggregation + residual + LN + ReLU =========
// Unshifted softmax: p = exp(logit); z and p*fs accumulated together in registers.
__global__ __launch_bounds__(256) void k_agg_ln(
    const float* __restrict__ attn,   // [4*32] this layer
    const float* __restrict__ lng, const float* __restrict__ lnb,
    float* __restrict__ outh)         // last-layer copy target or null
{
    int n = (blockIdx.x * 256 + threadIdx.x) >> 5;
    int lane = threadIdx.x & 31;
    if (n >= NN) return;

    float4 fdv = *(const float4*)(g_fd + (size_t)n * HIDD + lane * 4);
    float4 wa  = *(const float4*)(attn + lane * 4);

    int beg = g_rowptr[n], end = g_rowptr[n + 1];

    float z = 0.f;
    float m0 = 0.f, m1 = 0.f, m2 = 0.f, m3 = 0.f;
    int s_next = (beg < end) ? g_csr_src[beg] : 0;
    for (int i = beg; i < end; i++) {
        int s = s_next;
        if (i + 1 < end) s_next = g_csr_src[i + 1];
        float4 a = *(const float4*)(g_fs + (size_t)s * HIDD + lane * 4);
        float x0 = a.x + fdv.x; x0 = x0 > 0.f ? x0 : 0.2f * x0;
        float x1 = a.y + fdv.y; x1 = x1 > 0.f ? x1 : 0.2f * x1;
        float x2 = a.z + fdv.z; x2 = x2 > 0.f ? x2 : 0.2f * x2;
        float x3 = a.w + fdv.w; x3 = x3 > 0.f ? x3 : 0.2f * x3;
        float lg = x0 * wa.x + x1 * wa.y + x2 * wa.z + x3 * wa.w;
        lg += __shfl_xor_sync(0xffffffffu, lg, 4);
        lg += __shfl_xor_sync(0xffffffffu, lg, 2);
        lg += __shfl_xor_sync(0xffffffffu, lg, 1);   // all 8 lanes of head hold it
        float p = __expf(lg);
        z += p;
        m0 += p * a.x; m1 += p * a.y; m2 += p * a.z; m3 += p * a.w;
    }
    float inv_z = 1.f / z;
    m0 *= inv_z; m1 *= inv_z; m2 *= inv_z; m3 *= inv_z;

    // residual + LN + ReLU
    size_t base = (size_t)n * HIDD + lane * 4;
    float4 hv = *(const float4*)(g_h + base);
    float x0 = 2.f * hv.x + m0;
    float x1 = 2.f * hv.y + m1;
    float x2 = 2.f * hv.z + m2;
    float x3 = 2.f * hv.w + m3;
    float su = x0 + x1 + x2 + x3;
    #pragma unroll
    for (int o = 16; o; o >>= 1) su += __shfl_xor_sync(0xffffffffu, su, o);
    float mu = su * (1.f / 128.f);
    float d0 = x0 - mu, d1 = x1 - mu, d2 = x2 - mu, d3 = x3 - mu;
    float sv = d0 * d0 + d1 * d1 + d2 * d2 + d3 * d3;
    #pragma unroll
    for (int o = 16; o; o >>= 1) sv += __shfl_xor_sync(0xffffffffu, sv, o);
    float inv = rsqrtf(sv * (1.f / 128.f) + 1e-5f);
    float4 gg = *(const float4*)(lng + lane * 4);
    float4 bb = *(const float4*)(lnb + lane * 4);
    float y0 = fmaxf(d0 * inv * gg.x + bb.x, 0.f);
    float y1 = fmaxf(d1 * inv * gg.y + bb.y, 0.f);
    float y2 = fmaxf(d2 * inv * gg.z + bb.z, 0.f);
    float y3 = fmaxf(d3 * inv * gg.w + bb.w, 0.f);
    float4 y = { y0, y1, y2, y3 };
    *(float4*)(g_h + base) = y;
    if (outh) *(float4*)(outh + base) = y;
}

// ---------------- graph mean ----------------
__global__ void k_zero_out(float* __restrict__ out)
{
    if (threadIdx.x < 128) out[threadIdx.x] = 0.f;
}

__global__ void k_mean(float* __restrict__ out)
{
    int c = threadIdx.x;              // 128 threads = feature
    int chunk = (NN + gridDim.x - 1) / gridDim.x;
    int n0 = blockIdx.x * chunk;
    int n1 = n0 + chunk; if (n1 > NN) n1 = NN;
    float s = 0.f;
    for (int n = n0; n < n1; n++) s += g_h[(size_t)n * HIDD + c];
    atomicAdd(&out[c], s * (1.f / (float)NN));
}

// ---------------- launch ----------------
extern "C" void kernel_launch(void* const* d_in, const int* in_sizes, int n_in,
                              void* d_out, int out_size)
{
    const float* nf    = (const float*)d_in[0];
    const int*   src   = (const int*)  d_in[1];
    const int*   dst   = (const int*)  d_in[2];
    const float* W_in  = (const float*)d_in[3];
    const float* b_in  = (const float*)d_in[4];
    const float* W_src = (const float*)d_in[5];
    const float* b_src = (const float*)d_in[6];
    const float* W_dst = (const float*)d_in[7];
    const float* b_dst = (const float*)d_in[8];
    const float* attn  = (const float*)d_in[9];
    const float* ln_g  = (const float*)d_in[10];
    const float* ln_b  = (const float*)d_in[11];
    float* out = (float*)d_out;

    (void)in_sizes; (void)n_in; (void)out_size;

    const int gE = (NE2 + 255) / 256;
    const int gN = (NN + 255) / 256;

    // CSR build (dst-sorted), once per launch
    k_zero_cnt<<<gN, 256>>>();
    k_hist<<<gE, 256>>>(dst);
    k_scan1<<<NB, 256>>>();
    k_scan2<<<1, 256>>>();
    k_scan3<<<gN, 256>>>();
    k_fill<<<gE, 256>>>(src, dst);

    k_gemm_in<<<(NN + 63) / 64, 256>>>(nf, W_in, b_in);

    const int gNodeWarp = (NN * 32 + 255) / 256;
    dim3 gGemm((NN + 127) / 128, 2);

    for (int l = 0; l < 3; l++) {
        k_gemm_dual_tc<<<gGemm, 256>>>(
            W_src + (size_t)l * HIDD * HIDD, b_src + (size_t)l * HIDD,
            W_dst + (size_t)l * HIDD * HIDD, b_dst + (size_t)l * HIDD);
        k_agg_ln<<<gNodeWarp, 256>>>(
            attn + (size_t)l * HIDD,
            ln_g + (size_t)l * HIDD, ln_b + (size_t)l * HIDD,
            (l == 2) ? (out + HIDD) : nullptr);
    }

    k_zero_out<<<1, 128>>>(out);
    k_mean<<<500, 128>>>(out);
}

// round 9
// speedup vs baseline: 4.1884x; 1.0311x over previous
#include <cuda_runtime.h>
#include <math.h>
#include <stdint.h>

#define NN   50000
#define EE   800000
#define NE2  850000      // EE + NN self loops
#define HIDD 128
#define NB   196         // ceil(NN/256) scan blocks

// ---------------- scratch (device globals; no runtime allocation) ----------------
__device__ float g_h  [(size_t)NN * HIDD];
__device__ float g_fs [(size_t)NN * HIDD];
__device__ float g_fd [(size_t)NN * HIDD];
__device__ int   g_csr_src[NE2];
__device__ int   g_rowptr [NN + 1];
__device__ int   g_cursor [NN];             // doubles as histogram counts
__device__ int   g_bsum[NB];

// ================= CSR build (per launch; dst-only, layer-invariant) =============
__global__ void k_zero_cnt()
{
    int i = blockIdx.x * blockDim.x + threadIdx.x;
    if (i < NN) g_cursor[i] = 0;
}

__global__ void k_hist(const int* __restrict__ dst)
{
    int e = blockIdx.x * blockDim.x + threadIdx.x;
    if (e >= NE2) return;
    int d = (e < EE) ? dst[e] : e - EE;
    atomicAdd(&g_cursor[d], 1);
}

__global__ void k_scan1()
{
    __shared__ int s[256];
    int t = threadIdx.x, i = blockIdx.x * 256 + t;
    int v = (i < NN) ? g_cursor[i] : 0;
    s[t] = v; __syncthreads();
    for (int o = 1; o < 256; o <<= 1) {
        int x = (t >= o) ? s[t - o] : 0;
        __syncthreads();
        s[t] += x;
        __syncthreads();
    }
    if (i < NN) g_rowptr[i] = s[t] - v;          // block-local exclusive
    if (t == 255) g_bsum[blockIdx.x] = s[255];
}

// scan3 with inlined block-offset reduction (replaces old scan2+scan3)
__global__ void k_scan3()
{
    __shared__ int red[256];
    int t = threadIdx.x;
    int bid = blockIdx.x;
    int v = (t < NB && t < bid) ? g_bsum[t] : 0;
    red[t] = v; __syncthreads();
    #pragma unroll
    for (int o = 128; o; o >>= 1) {
        if (t < o) red[t] += red[t + o];
        __syncthreads();
    }
    int boff = red[0];
    int i = bid * 256 + t;
    if (i < NN) {
        int rp = g_rowptr[i] + boff;
        g_rowptr[i] = rp;
        g_cursor[i] = rp;                        // fill cursor
    }
    if (i == 0) g_rowptr[NN] = NE2;
}

__global__ void k_fill(const int* __restrict__ src, const int* __restrict__ dst)
{
    int e = blockIdx.x * blockDim.x + threadIdx.x;
    if (e >= NE2) return;
    int s, d;
    if (e < EE) { s = src[e]; d = dst[e]; } else { s = e - EE; d = s; }
    int pos = atomicAdd(&g_cursor[d], 1);
    g_csr_src[pos] = s;
}

// ===================== tf32 tensor-core GEMM machinery ===========================
// Raw fp32 bits fed to tf32 mma: HW reads the upper 19 bits (truncation round).
__device__ __forceinline__ void mma_tf32(
    float& c0, float& c1, float& c2, float& c3,
    uint32_t a0, uint32_t a1, uint32_t a2, uint32_t a3,
    uint32_t b0, uint32_t b1)
{
    asm volatile(
        "mma.sync.aligned.m16n8k8.row.col.f32.tf32.tf32.f32 "
        "{%0,%1,%2,%3},{%4,%5,%6,%7},{%8,%9},{%0,%1,%2,%3};"
        : "+f"(c0), "+f"(c1), "+f"(c2), "+f"(c3)
        : "r"(a0), "r"(a1), "r"(a2), "r"(a3), "r"(b0), "r"(b1));
}

__device__ __forceinline__ void cp_async16(void* dst, const void* src, bool pred)
{
    uint32_t d = (uint32_t)__cvta_generic_to_shared(dst);
    int n = pred ? 16 : 0;
    asm volatile("cp.async.cg.shared.global [%0], [%1], 16, %2;"
                 :: "r"(d), "l"(src), "r"(n));
}
#define CP_COMMIT() asm volatile("cp.async.commit_group;")
#define CP_WAIT(N)  asm volatile("cp.async.wait_group %0;" :: "n"(N))

// smem layout (dynamic): As[2][128][36], Bs[2][32][132]
#define A_ST  (128 * 36)
#define B_ST  (32 * 132)
#define SMEM_BYTES ((2 * A_ST + 2 * B_ST) * 4)

// KTOT = 128 (dual) or 64 (input proj). grid.y picks the (W,b,F) set for dual.
template<int KTOT, int AROW>
__device__ __forceinline__ void gemm_tc_body(
    const float* __restrict__ A, const float* __restrict__ W,
    const float* __restrict__ bias, float* __restrict__ F)
{
    extern __shared__ float sm[];
    float* AsB = sm;
    float* BsB = sm + 2 * A_ST;

    int tid = threadIdx.x;
    int lane = tid & 31, wid = tid >> 5;
    int wm = wid >> 2, wn = wid & 3;          // warp grid 2(m) x 4(n)
    int l4 = lane >> 2, lk = lane & 3;
    int row0 = blockIdx.x * 128;

    float c[4][4][4];
    #pragma unroll
    for (int i = 0; i < 4; i++)
        #pragma unroll
        for (int j = 0; j < 4; j++)
            #pragma unroll
            for (int q = 0; q < 4; q++) c[i][j][q] = 0.f;

    auto load_tiles = [&](int k0, int st) {
        float* As = AsB + st * A_ST;
        float* Bs = BsB + st * B_ST;
        #pragma unroll
        for (int i = 0; i < 4; i++) {
            int cix = tid + i * 256;
            int r = cix >> 3, cc = (cix & 7) * 4;
            int row = row0 + r;
            cp_async16(&As[r * 36 + cc], &A[(size_t)row * AROW + k0 + cc], row < NN);
        }
        #pragma unroll
        for (int i = 0; i < 4; i++) {
            int cix = tid + i * 256;
            int kk = cix >> 5, cc = (cix & 31) * 4;
            cp_async16(&Bs[kk * 132 + cc], &W[(size_t)(k0 + kk) * HIDD + cc], true);
        }
        CP_COMMIT();
    };

    const int NIT = KTOT / 32;
    load_tiles(0, 0);
    #pragma unroll
    for (int it = 0; it < NIT; it++) {
        int st = it & 1;
        if (it + 1 < NIT) { load_tiles((it + 1) * 32, st ^ 1); CP_WAIT(1); }
        else              { CP_WAIT(0); }
        __syncthreads();

        const float* As = AsB + st * A_ST;
        const float* Bs = BsB + st * B_ST;
        #pragma unroll
        for (int ks = 0; ks < 4; ks++) {
            int kc = ks * 8 + lk;
            uint32_t a[4][4], b[4][2];
            #pragma unroll
            for (int mf = 0; mf < 4; mf++) {
                int m0 = wm * 64 + mf * 16;
                a[mf][0] = __float_as_uint(As[(m0 + l4    ) * 36 + kc    ]);
                a[mf][1] = __float_as_uint(As[(m0 + l4 + 8) * 36 + kc    ]);
                a[mf][2] = __float_as_uint(As[(m0 + l4    ) * 36 + kc + 4]);
                a[mf][3] = __float_as_uint(As[(m0 + l4 + 8) * 36 + kc + 4]);
            }
            #pragma unroll
            for (int nf = 0; nf < 4; nf++) {
                int n0 = wn * 32 + nf * 8 + l4;
                b[nf][0] = __float_as_uint(Bs[(ks * 8 + lk    ) * 132 + n0]);
                b[nf][1] = __float_as_uint(Bs[(ks * 8 + lk + 4) * 132 + n0]);
            }
            #pragma unroll
            for (int mf = 0; mf < 4; mf++)
                #pragma unroll
                for (int nf = 0; nf < 4; nf++)
                    mma_tf32(c[mf][nf][0], c[mf][nf][1], c[mf][nf][2], c[mf][nf][3],
                             a[mf][0], a[mf][1], a[mf][2], a[mf][3],
                             b[nf][0], b[nf][1]);
        }
        __syncthreads();
    }

    // epilogue: bias + store
    #pragma unroll
    for (int mf = 0; mf < 4; mf++) {
        int r = row0 + wm * 64 + mf * 16 + l4;
        #pragma unroll
        for (int nf = 0; nf < 4; nf++) {
            int col = wn * 32 + nf * 8 + lk * 2;
            float2 bb = *(const float2*)&bias[col];
            if (r < NN) {
                float2 o = { c[mf][nf][0] + bb.x, c[mf][nf][1] + bb.y };
                *(float2*)&F[(size_t)r * HIDD + col] = o;
            }
            if (r + 8 < NN) {
                float2 o = { c[mf][nf][2] + bb.x, c[mf][nf][3] + bb.y };
                *(float2*)&F[(size_t)(r + 8) * HIDD + col] = o;
            }
        }
    }
}

__global__ __launch_bounds__(256) void k_gemm_in_tc(
    const float* __restrict__ A,     // [NN,64]
    const float* __restrict__ W,     // [64,128]
    const float* __restrict__ bias)
{
    gemm_tc_body<64, 64>(A, W, bias, g_h);
}

__global__ __launch_bounds__(256) void k_gemm_dual_tc(
    const float* __restrict__ Ws, const float* __restrict__ bs,
    const float* __restrict__ Wd, const float* __restrict__ bd)
{
    if (blockIdx.y) gemm_tc_body<128, 128>(g_h, Wd, bd, g_fd);
    else            gemm_tc_body<128, 128>(g_h, Ws, bs, g_fs);
}

// ====== fused single-pass attention + aggregation + residual + LN + ReLU =========
__global__ __launch_bounds__(256) void k_agg_ln(
    const float* __restrict__ attn,   // [4*32] this layer
    const float* __restrict__ lng, const float* __restrict__ lnb,
    float* __restrict__ outh)         // last-layer copy target or null
{
    int n = (blockIdx.x * 256 + threadIdx.x) >> 5;
    int lane = threadIdx.x & 31;
    if (n >= NN) return;

    float4 fdv = *(const float4*)(g_fd + (size_t)n * HIDD + lane * 4);
    float4 wa  = *(const float4*)(attn + lane * 4);

    int beg = g_rowptr[n], end = g_rowptr[n + 1];

    float z = 0.f;
    float m0 = 0.f, m1 = 0.f, m2 = 0.f, m3 = 0.f;
    int s_next = (beg < end) ? g_csr_src[beg] : 0;
    for (int i = beg; i < end; i++) {
        int s = s_next;
        if (i + 1 < end) s_next = g_csr_src[i + 1];
        float4 a = *(const float4*)(g_fs + (size_t)s * HIDD + lane * 4);
        float x0 = a.x + fdv.x; x0 = x0 > 0.f ? x0 : 0.2f * x0;
        float x1 = a.y + fdv.y; x1 = x1 > 0.f ? x1 : 0.2f * x1;
        float x2 = a.z + fdv.z; x2 = x2 > 0.f ? x2 : 0.2f * x2;
        float x3 = a.w + fdv.w; x3 = x3 > 0.f ? x3 : 0.2f * x3;
        float lg = x0 * wa.x + x1 * wa.y + x2 * wa.z + x3 * wa.w;
        lg += __shfl_xor_sync(0xffffffffu, lg, 4);
        lg += __shfl_xor_sync(0xffffffffu, lg, 2);
        lg += __shfl_xor_sync(0xffffffffu, lg, 1);   // all 8 lanes of head hold it
        float p = __expf(lg);
        z += p;
        m0 += p * a.x; m1 += p * a.y; m2 += p * a.z; m3 += p * a.w;
    }
    float inv_z = 1.f / z;
    m0 *= inv_z; m1 *= inv_z; m2 *= inv_z; m3 *= inv_z;

    // residual + LN + ReLU
    size_t base = (size_t)n * HIDD + lane * 4;
    float4 hv = *(const float4*)(g_h + base);
    float x0 = 2.f * hv.x + m0;
    float x1 = 2.f * hv.y + m1;
    float x2 = 2.f * hv.z + m2;
    float x3 = 2.f * hv.w + m3;
    float su = x0 + x1 + x2 + x3;
    #pragma unroll
    for (int o = 16; o; o >>= 1) su += __shfl_xor_sync(0xffffffffu, su, o);
    float mu = su * (1.f / 128.f);
    float d0 = x0 - mu, d1 = x1 - mu, d2 = x2 - mu, d3 = x3 - mu;
    float sv = d0 * d0 + d1 * d1 + d2 * d2 + d3 * d3;
    #pragma unroll
    for (int o = 16; o; o >>= 1) sv += __shfl_xor_sync(0xffffffffu, sv, o);
    float inv = rsqrtf(sv * (1.f / 128.f) + 1e-5f);
    float4 gg = *(const float4*)(lng + lane * 4);
    float4 bb = *(const float4*)(lnb + lane * 4);
    float y0 = fmaxf(d0 * inv * gg.x + bb.x, 0.f);
    float y1 = fmaxf(d1 * inv * gg.y + bb.y, 0.f);
    float y2 = fmaxf(d2 * inv * gg.z + bb.z, 0.f);
    float y3 = fmaxf(d3 * inv * gg.w + bb.w, 0.f);
    float4 y = { y0, y1, y2, y3 };
    *(float4*)(g_h + base) = y;
    if (outh) *(float4*)(outh + base) = y;
}

// ---------------- graph mean ----------------
__global__ void k_zero_out(float* __restrict__ out)
{
    if (threadIdx.x < 128) out[threadIdx.x] = 0.f;
}

__global__ void k_mean(float* __restrict__ out)
{
    int c = threadIdx.x;              // 128 threads = feature
    int chunk = (NN + gridDim.x - 1) / gridDim.x;
    int n0 = blockIdx.x * chunk;
    int n1 = n0 + chunk; if (n1 > NN) n1 = NN;
    float s = 0.f;
    for (int n = n0; n < n1; n++) s += g_h[(size_t)n * HIDD + c];
    atomicAdd(&out[c], s * (1.f / (float)NN));
}

// ---------------- launch ----------------
extern "C" void kernel_launch(void* const* d_in, const int* in_sizes, int n_in,
                              void* d_out, int out_size)
{
    const float* nf    = (const float*)d_in[0];
    const int*   src   = (const int*)  d_in[1];
    const int*   dst   = (const int*)  d_in[2];
    const float* W_in  = (const float*)d_in[3];
    const float* b_in  = (const float*)d_in[4];
    const float* W_src = (const float*)d_in[5];
    const float* b_src = (const float*)d_in[6];
    const float* W_dst = (const float*)d_in[7];
    const float* b_dst = (const float*)d_in[8];
    const float* attn  = (const float*)d_in[9];
    const float* ln_g  = (const float*)d_in[10];
    const float* ln_b  = (const float*)d_in[11];
    float* out = (float*)d_out;

    (void)in_sizes; (void)n_in; (void)out_size;

    cudaFuncSetAttribute(k_gemm_in_tc,
        cudaFuncAttributeMaxDynamicSharedMemorySize, SMEM_BYTES);
    cudaFuncSetAttribute(k_gemm_dual_tc,
        cudaFuncAttributeMaxDynamicSharedMemorySize, SMEM_BYTES);

    const int gE = (NE2 + 255) / 256;
    const int gN = (NN + 255) / 256;

    // CSR build (dst-sorted), once per launch
    k_zero_cnt<<<gN, 256>>>();
    k_hist<<<gE, 256>>>(dst);
    k_scan1<<<NB, 256>>>();
    k_scan3<<<gN, 256>>>();
    k_fill<<<gE, 256>>>(src, dst);

    k_gemm_in_tc<<<(NN + 127) / 128, 256, SMEM_BYTES>>>(nf, W_in, b_in);

    const int gNodeWarp = (NN * 32 + 255) / 256;
    dim3 gGemm((NN + 127) / 128, 2);

    for (int l = 0; l < 3; l++) {
        k_gemm_dual_tc<<<gGemm, 256, SMEM_BYTES>>>(
            W_src + (size_t)l * HIDD * HIDD, b_src + (size_t)l * HIDD,
            W_dst + (size_t)l * HIDD * HIDD, b_dst + (size_t)l * HIDD);
        k_agg_ln<<<gNodeWarp, 256>>>(
            attn + (size_t)l * HIDD,
            ln_g + (size_t)l * HIDD, ln_b + (size_t)l * HIDD,
            (l == 2) ? (out + HIDD) : nullptr);
    }

    k_zero_out<<<1, 128>>>(out);
    k_mean<<<500, 128>>>(out);
}

// round 10
// speedup vs baseline: 4.4067x; 1.0521x over previous
#include <cuda_runtime.h>
#include <math.h>
#include <stdint.h>

#define NN   50000
#define EE   800000
#define NE2  850000      // EE + NN self loops
#define HIDD 128
#define NB   196         // ceil(NN/256) scan blocks

// ---------------- scratch (device globals; no runtime allocation) ----------------
__device__ float g_h  [(size_t)NN * HIDD];
__device__ float g_fs [(size_t)NN * HIDD];
__device__ float g_fd [(size_t)NN * HIDD];
__device__ int   g_csr_src[NE2];
__device__ int   g_rowptr [NN + 1];
__device__ int   g_cursor [NN];             // doubles as histogram counts
__device__ int   g_bsum[NB];

// ================= CSR build (per launch; dst-only, layer-invariant) =============
__global__ void k_zero_cnt()
{
    int i = blockIdx.x * blockDim.x + threadIdx.x;
    if (i < NN) g_cursor[i] = 0;
}

__global__ void k_hist(const int* __restrict__ dst)
{
    int e = blockIdx.x * blockDim.x + threadIdx.x;
    if (e >= NE2) return;
    int d = (e < EE) ? dst[e] : e - EE;
    atomicAdd(&g_cursor[d], 1);
}

__global__ void k_scan1()
{
    __shared__ int s[256];
    int t = threadIdx.x, i = blockIdx.x * 256 + t;
    int v = (i < NN) ? g_cursor[i] : 0;
    s[t] = v; __syncthreads();
    for (int o = 1; o < 256; o <<= 1) {
        int x = (t >= o) ? s[t - o] : 0;
        __syncthreads();
        s[t] += x;
        __syncthreads();
    }
    if (i < NN) g_rowptr[i] = s[t] - v;          // block-local exclusive
    if (t == 255) g_bsum[blockIdx.x] = s[255];
}

// scan3 with inlined block-offset reduction
__global__ void k_scan3()
{
    __shared__ int red[256];
    int t = threadIdx.x;
    int bid = blockIdx.x;
    int v = (t < NB && t < bid) ? g_bsum[t] : 0;
    red[t] = v; __syncthreads();
    #pragma unroll
    for (int o = 128; o; o >>= 1) {
        if (t < o) red[t] += red[t + o];
        __syncthreads();
    }
    int boff = red[0];
    int i = bid * 256 + t;
    if (i < NN) {
        int rp = g_rowptr[i] + boff;
        g_rowptr[i] = rp;
        g_cursor[i] = rp;                        // fill cursor
    }
    if (i == 0) g_rowptr[NN] = NE2;
}

__global__ void k_fill(const int* __restrict__ src, const int* __restrict__ dst)
{
    int e = blockIdx.x * blockDim.x + threadIdx.x;
    if (e >= NE2) return;
    int s, d;
    if (e < EE) { s = src[e]; d = dst[e]; } else { s = e - EE; d = s; }
    int pos = atomicAdd(&g_cursor[d], 1);
    g_csr_src[pos] = s;
}

// ===================== tf32 tensor-core GEMM machinery ===========================
__device__ __forceinline__ uint32_t f2tf(float x)   // round-to-nearest tf32
{
    uint32_t r;
    asm("cvt.rna.tf32.f32 %0, %1;" : "=r"(r) : "f"(x));
    return r;
}

__device__ __forceinline__ void mma_tf32(
    float& c0, float& c1, float& c2, float& c3,
    uint32_t a0, uint32_t a1, uint32_t a2, uint32_t a3,
    uint32_t b0, uint32_t b1)
{
    asm volatile(
        "mma.sync.aligned.m16n8k8.row.col.f32.tf32.tf32.f32 "
        "{%0,%1,%2,%3},{%4,%5,%6,%7},{%8,%9},{%0,%1,%2,%3};"
        : "+f"(c0), "+f"(c1), "+f"(c2), "+f"(c3)
        : "r"(a0), "r"(a1), "r"(a2), "r"(a3), "r"(b0), "r"(b1));
}

__device__ __forceinline__ void cp_async16(void* dst, const void* src, bool pred)
{
    uint32_t d = (uint32_t)__cvta_generic_to_shared(dst);
    int n = pred ? 16 : 0;
    asm volatile("cp.async.cg.shared.global [%0], [%1], 16, %2;"
                 :: "r"(d), "l"(src), "r"(n));
}
#define CP_COMMIT() asm volatile("cp.async.commit_group;")
#define CP_WAIT(N)  asm volatile("cp.async.wait_group %0;" :: "n"(N))

// smem layout (dynamic): As[2][128][36], Bs[2][32][132]
#define A_ST  (128 * 36)
#define B_ST  (32 * 132)
#define SMEM_BYTES ((2 * A_ST + 2 * B_ST) * 4)

template<int KTOT, int AROW>
__device__ __forceinline__ void gemm_tc_body(
    const float* __restrict__ A, const float* __restrict__ W,
    const float* __restrict__ bias, float* __restrict__ F)
{
    extern __shared__ float sm[];
    float* AsB = sm;
    float* BsB = sm + 2 * A_ST;

    int tid = threadIdx.x;
    int lane = tid & 31, wid = tid >> 5;
    int wm = wid >> 2, wn = wid & 3;          // warp grid 2(m) x 4(n)
    int l4 = lane >> 2, lk = lane & 3;
    int row0 = blockIdx.x * 128;

    float c[4][4][4];
    #pragma unroll
    for (int i = 0; i < 4; i++)
        #pragma unroll
        for (int j = 0; j < 4; j++)
            #pragma unroll
            for (int q = 0; q < 4; q++) c[i][j][q] = 0.f;

    auto load_tiles = [&](int k0, int st) {
        float* As = AsB + st * A_ST;
        float* Bs = BsB + st * B_ST;
        #pragma unroll
        for (int i = 0; i < 4; i++) {
            int cix = tid + i * 256;
            int r = cix >> 3, cc = (cix & 7) * 4;
            int row = row0 + r;
            cp_async16(&As[r * 36 + cc], &A[(size_t)row * AROW + k0 + cc], row < NN);
        }
        #pragma unroll
        for (int i = 0; i < 4; i++) {
            int cix = tid + i * 256;
            int kk = cix >> 5, cc = (cix & 31) * 4;
            cp_async16(&Bs[kk * 132 + cc], &W[(size_t)(k0 + kk) * HIDD + cc], true);
        }
        CP_COMMIT();
    };

    const int NIT = KTOT / 32;
    load_tiles(0, 0);
    #pragma unroll
    for (int it = 0; it < NIT; it++) {
        int st = it & 1;
        if (it + 1 < NIT) { load_tiles((it + 1) * 32, st ^ 1); CP_WAIT(1); }
        else              { CP_WAIT(0); }
        __syncthreads();

        const float* As = AsB + st * A_ST;
        const float* Bs = BsB + st * B_ST;
        #pragma unroll
        for (int ks = 0; ks < 4; ks++) {
            int kc = ks * 8 + lk;
            uint32_t a[4][4], b[4][2];
            #pragma unroll
            for (int mf = 0; mf < 4; mf++) {
                int m0 = wm * 64 + mf * 16;
                a[mf][0] = f2tf(As[(m0 + l4    ) * 36 + kc    ]);
                a[mf][1] = f2tf(As[(m0 + l4 + 8) * 36 + kc    ]);
                a[mf][2] = f2tf(As[(m0 + l4    ) * 36 + kc + 4]);
                a[mf][3] = f2tf(As[(m0 + l4 + 8) * 36 + kc + 4]);
            }
            #pragma unroll
            for (int nf = 0; nf < 4; nf++) {
                int n0 = wn * 32 + nf * 8 + l4;
                b[nf][0] = f2tf(Bs[(ks * 8 + lk    ) * 132 + n0]);
                b[nf][1] = f2tf(Bs[(ks * 8 + lk + 4) * 132 + n0]);
            }
            #pragma unroll
            for (int mf = 0; mf < 4; mf++)
                #pragma unroll
                for (int nf = 0; nf < 4; nf++)
                    mma_tf32(c[mf][nf][0], c[mf][nf][1], c[mf][nf][2], c[mf][nf][3],
                             a[mf][0], a[mf][1], a[mf][2], a[mf][3],
                             b[nf][0], b[nf][1]);
        }
        __syncthreads();
    }

    // epilogue: bias + store
    #pragma unroll
    for (int mf = 0; mf < 4; mf++) {
        int r = row0 + wm * 64 + mf * 16 + l4;
        #pragma unroll
        for (int nf = 0; nf < 4; nf++) {
            int col = wn * 32 + nf * 8 + lk * 2;
            float2 bb = *(const float2*)&bias[col];
            if (r < NN) {
                float2 o = { c[mf][nf][0] + bb.x, c[mf][nf][1] + bb.y };
                *(float2*)&F[(size_t)r * HIDD + col] = o;
            }
            if (r + 8 < NN) {
                float2 o = { c[mf][nf][2] + bb.x, c[mf][nf][3] + bb.y };
                *(float2*)&F[(size_t)(r + 8) * HIDD + col] = o;
            }
        }
    }
}

__global__ __launch_bounds__(256) void k_gemm_in_tc(
    const float* __restrict__ A,     // [NN,64]
    const float* __restrict__ W,     // [64,128]
    const float* __restrict__ bias)
{
    gemm_tc_body<64, 64>(A, W, bias, g_h);
}

__global__ __launch_bounds__(256) void k_gemm_dual_tc(
    const float* __restrict__ Ws, const float* __restrict__ bs,
    const float* __restrict__ Wd, const float* __restrict__ bd)
{
    if (blockIdx.y) gemm_tc_body<128, 128>(g_h, Wd, bd, g_fd);
    else            gemm_tc_body<128, 128>(g_h, Ws, bs, g_fs);
}

// ====== fused single-pass attention + aggregation + residual + LN + ReLU =========
// 2-edge unrolled: two independent gather/logit/exp chains interleaved for ILP.
__global__ __launch_bounds__(256) void k_agg_ln(
    const float* __restrict__ attn,   // [4*32] this layer
    const float* __restrict__ lng, const float* __restrict__ lnb,
    float* __restrict__ outh)         // last-layer copy target or null
{
    int n = (blockIdx.x * 256 + threadIdx.x) >> 5;
    int lane = threadIdx.x & 31;
    if (n >= NN) return;

    float4 fdv = *(const float4*)(g_fd + (size_t)n * HIDD + lane * 4);
    float4 wa  = *(const float4*)(attn + lane * 4);

    int beg = g_rowptr[n], end = g_rowptr[n + 1];

    float z = 0.f;
    float m0 = 0.f, m1 = 0.f, m2 = 0.f, m3 = 0.f;

    int i = beg;
    // peel odd edge so the main loop runs in pairs
    if ((end - beg) & 1) {
        int s = g_csr_src[i]; i++;
        float4 a = *(const float4*)(g_fs + (size_t)s * HIDD + lane * 4);
        float x0 = a.x + fdv.x; x0 = x0 > 0.f ? x0 : 0.2f * x0;
        float x1 = a.y + fdv.y; x1 = x1 > 0.f ? x1 : 0.2f * x1;
        float x2 = a.z + fdv.z; x2 = x2 > 0.f ? x2 : 0.2f * x2;
        float x3 = a.w + fdv.w; x3 = x3 > 0.f ? x3 : 0.2f * x3;
        float lg = x0 * wa.x + x1 * wa.y + x2 * wa.z + x3 * wa.w;
        lg += __shfl_xor_sync(0xffffffffu, lg, 4);
        lg += __shfl_xor_sync(0xffffffffu, lg, 2);
        lg += __shfl_xor_sync(0xffffffffu, lg, 1);
        float p = __expf(lg);
        z += p;
        m0 += p * a.x; m1 += p * a.y; m2 += p * a.z; m3 += p * a.w;
    }
    for (; i < end; i += 2) {
        int s0 = g_csr_src[i];
        int s1 = g_csr_src[i + 1];
        float4 a0 = *(const float4*)(g_fs + (size_t)s0 * HIDD + lane * 4);
        float4 a1 = *(const float4*)(g_fs + (size_t)s1 * HIDD + lane * 4);

        float u0 = a0.x + fdv.x; u0 = u0 > 0.f ? u0 : 0.2f * u0;
        float u1 = a0.y + fdv.y; u1 = u1 > 0.f ? u1 : 0.2f * u1;
        float u2 = a0.z + fdv.z; u2 = u2 > 0.f ? u2 : 0.2f * u2;
        float u3 = a0.w + fdv.w; u3 = u3 > 0.f ? u3 : 0.2f * u3;
        float v0 = a1.x + fdv.x; v0 = v0 > 0.f ? v0 : 0.2f * v0;
        float v1 = a1.y + fdv.y; v1 = v1 > 0.f ? v1 : 0.2f * v1;
        float v2 = a1.z + fdv.z; v2 = v2 > 0.f ? v2 : 0.2f * v2;
        float v3 = a1.w + fdv.w; v3 = v3 > 0.f ? v3 : 0.2f * v3;

        float lgA = u0 * wa.x + u1 * wa.y + u2 * wa.z + u3 * wa.w;
        float lgB = v0 * wa.x + v1 * wa.y + v2 * wa.z + v3 * wa.w;
        lgA += __shfl_xor_sync(0xffffffffu, lgA, 4);
        lgB += __shfl_xor_sync(0xffffffffu, lgB, 4);
        lgA += __shfl_xor_sync(0xffffffffu, lgA, 2);
        lgB += __shfl_xor_sync(0xffffffffu, lgB, 2);
        lgA += __shfl_xor_sync(0xffffffffu, lgA, 1);
        lgB += __shfl_xor_sync(0xffffffffu, lgB, 1);

        float pA = __expf(lgA);
        float pB = __expf(lgB);
        z += pA + pB;
        m0 += pA * a0.x + pB * a1.x;
        m1 += pA * a0.y + pB * a1.y;
        m2 += pA * a0.z + pB * a1.z;
        m3 += pA * a0.w + pB * a1.w;
    }
    float inv_z = 1.f / z;
    m0 *= inv_z; m1 *= inv_z; m2 *= inv_z; m3 *= inv_z;

    // residual + LN + ReLU
    size_t base = (size_t)n * HIDD + lane * 4;
    float4 hv = *(const float4*)(g_h + base);
    float x0 = 2.f * hv.x + m0;
    float x1 = 2.f * hv.y + m1;
    float x2 = 2.f * hv.z + m2;
    float x3 = 2.f * hv.w + m3;
    float su = x0 + x1 + x2 + x3;
    #pragma unroll
    for (int o = 16; o; o >>= 1) su += __shfl_xor_sync(0xffffffffu, su, o);
    float mu = su * (1.f / 128.f);
    float d0 = x0 - mu, d1 = x1 - mu, d2 = x2 - mu, d3 = x3 - mu;
    float sv = d0 * d0 + d1 * d1 + d2 * d2 + d3 * d3;
    #pragma unroll
    for (int o = 16; o; o >>= 1) sv += __shfl_xor_sync(0xffffffffu, sv, o);
    float inv = rsqrtf(sv * (1.f / 128.f) + 1e-5f);
    float4 gg = *(const float4*)(lng + lane * 4);
    float4 bb = *(const float4*)(lnb + lane * 4);
    float y0 = fmaxf(d0 * inv * gg.x + bb.x, 0.f);
    float y1 = fmaxf(d1 * inv * gg.y + bb.y, 0.f);
    float y2 = fmaxf(d2 * inv * gg.z + bb.z, 0.f);
    float y3 = fmaxf(d3 * inv * gg.w + bb.w, 0.f);
    float4 y = { y0, y1, y2, y3 };
    *(float4*)(g_h + base) = y;
    if (outh) *(float4*)(outh + base) = y;
}

// ---------------- graph mean ----------------
__global__ void k_zero_out(float* __restrict__ out)
{
    if (threadIdx.x < 128) out[threadIdx.x] = 0.f;
}

__global__ void k_mean(float* __restrict__ out)
{
    int c = threadIdx.x;              // 128 threads = feature
    int chunk = (NN + gridDim.x - 1) / gridDim.x;
    int n0 = blockIdx.x * chunk;
    int n1 = n0 + chunk; if (n1 > NN) n1 = NN;
    float s = 0.f;
    for (int n = n0; n < n1; n++) s += g_h[(size_t)n * HIDD + c];
    atomicAdd(&out[c], s * (1.f / (float)NN));
}

// ---------------- launch ----------------
extern "C" void kernel_launch(void* const* d_in, const int* in_sizes, int n_in,
                              void* d_out, int out_size)
{
    const float* nf    = (const float*)d_in[0];
    const int*   src   = (const int*)  d_in[1];
    const int*   dst   = (const int*)  d_in[2];
    const float* W_in  = (const float*)d_in[3];
    const float* b_in  = (const float*)d_in[4];
    const float* W_src = (const float*)d_in[5];
    const float* b_src = (const float*)d_in[6];
    const float* W_dst = (const float*)d_in[7];
    const float* b_dst = (const float*)d_in[8];
    const float* attn  = (const float*)d_in[9];
    const float* ln_g  = (const float*)d_in[10];
    const float* ln_b  = (const float*)d_in[11];
    float* out = (float*)d_out;

    (void)in_sizes; (void)n_in; (void)out_size;

    cudaFuncSetAttribute(k_gemm_in_tc,
        cudaFuncAttributeMaxDynamicSharedMemorySize, SMEM_BYTES);
    cudaFuncSetAttribute(k_gemm_dual_tc,
        cudaFuncAttributeMaxDynamicSharedMemorySize, SMEM_BYTES);

    const int gE = (NE2 + 255) / 256;
    const int gN = (NN + 255) / 256;

    // CSR build (dst-sorted), once per launch
    k_zero_cnt<<<gN, 256>>>();
    k_hist<<<gE, 256>>>(dst);
    k_scan1<<<NB, 256>>>();
    k_scan3<<<gN, 256>>>();
    k_fill<<<gE, 256>>>(src, dst);

    k_gemm_in_tc<<<(NN + 127) / 128, 256, SMEM_BYTES>>>(nf, W_in, b_in);

    const int gNodeWarp = (NN * 32 + 255) / 256;
    dim3 gGemm((NN + 127) / 128, 2);

    for (int l = 0; l < 3; l++) {
        k_gemm_dual_tc<<<gGemm, 256, SMEM_BYTES>>>(
            W_src + (size_t)l * HIDD * HIDD, b_src + (size_t)l * HIDD,
            W_dst + (size_t)l * HIDD * HIDD, b_dst + (size_t)l * HIDD);
        k_agg_ln<<<gNodeWarp, 256>>>(
            attn + (size_t)l * HIDD,
            ln_g + (size_t)l * HIDD, ln_b + (size_t)l * HIDD,
            (l == 2) ? (out + HIDD) : nullptr);
    }

    k_zero_out<<<1, 128>>>(out);
    k_mean<<<500, 128>>>(out);
}